// round 5
// baseline (speedup 1.0000x reference)
#include <cuda_runtime.h>
#include <math.h>
#include <cstdint>

#define FRAMES 256
#define PATCHES 64
#define DIMX 512
#define HEADS 8
#define DH 64
#define DFF 1024
#define KPROJ 128
#define NT 257              // temporal seq len (cls + 256 frames)
#define NS 65               // spatial seq len (cls + 64 patches)
#define MT (PATCHES * NT)   // 16448 rows temporal
#define MS (FRAMES * NS)    // 16640 rows spatial

// ---------------- scratch (device globals; no allocation allowed) ----------
__device__ float g_X1[MT * DIMX];
__device__ float g_QKV1[MT * 3 * DIMX];
__device__ float g_O1[MT * DIMX];
__device__ float g_Y1[MT * DIMX];
__device__ float g_X2[MS * DIMX];
__device__ float g_QKV2[MS * 3 * DIMX];
__device__ float g_KE[FRAMES * HEADS * KPROJ * DH];
__device__ float g_VE[FRAMES * HEADS * KPROJ * DH];
__device__ float g_O2[MS * DIMX];
__device__ float g_Y2[MS * DIMX];
__device__ float g_H[MS * DFF];

// ---------------- gathers ---------------------------------------------------
__global__ void gather_temporal(const float* __restrict__ x) {
    int idx = blockIdx.x * blockDim.x + threadIdx.x;
    if (idx >= MT * DIMX) return;
    int d = idx & (DIMX - 1);
    int row = idx >> 9;
    int t = row % NT;
    int pb = row / NT;
    int src = (t == 0) ? 0 : (1 + (t - 1) * PATCHES + pb);
    g_X1[idx] = x[(size_t)src * DIMX + d];
}

__global__ void gather_spatial() {
    int idx = blockIdx.x * blockDim.x + threadIdx.x;
    if (idx >= MS * DIMX) return;
    int d = idx & (DIMX - 1);
    int row = idx >> 9;
    int s = row % NS;
    int fb = row / NS;
    int srow = (s == 0) ? ((fb & 63) * NT) : ((s - 1) * NT + 1 + fb);
    g_X2[idx] = g_Y1[(size_t)srow * DIMX + d];
}

// ---------------- tf32 tensor-core GEMM -------------------------------------
// C[M,N] = A[M,K] @ B[K,N], 128x128x32 tiles, 8 warps of 64x32, mma.m16n8k8.tf32
// 3-stage cp.async ring, one barrier per k-tile.
// EPI: 0 = none, 1 = +R, 2 = gelu(+bias), 3 = +bias +R
#define ASTR 36    // floats per A smem row   (16B-phase shift per row)
#define BSTR 136   // floats per B smem row   (stride mod 32 banks = 8 -> conflict-free)
#define A_TILE (128 * ASTR)
#define B_TILE (32 * BSTR)
#define NSTAGE 3
#define GEMM_SMEM (NSTAGE * (A_TILE + B_TILE) * 4)

__device__ __forceinline__ void cp_async16(uint32_t dst, const float* src, int srcsize) {
    asm volatile("cp.async.cg.shared.global [%0], [%1], 16, %2;\n"
                 :: "r"(dst), "l"(src), "r"(srcsize));
}

template <int EPI>
__global__ void __launch_bounds__(256)
tf32_gemm(const float* __restrict__ A, const float* __restrict__ B,
          float* __restrict__ C, const float* __restrict__ bias,
          const float* __restrict__ R, int M, int N, int K) {
    extern __shared__ float smem[];
    float* As = smem;                        // [NSTAGE][128][ASTR]
    float* Bs = smem + NSTAGE * A_TILE;      // [NSTAGE][32][BSTR]
    uint32_t sA = (uint32_t)__cvta_generic_to_shared(As);
    uint32_t sB = (uint32_t)__cvta_generic_to_shared(Bs);

    int tid = threadIdx.x;
    int lane = tid & 31, warp = tid >> 5;
    int wm = warp & 1, wn = warp >> 1;   // 2 x 4 warp grid
    int m0 = blockIdx.y * 128;
    int n0 = blockIdx.x * 128;

    int aRow = lane & 15;
    int aCol4 = (lane >> 4) * 4;
    uint32_t aBase[4];
#pragma unroll
    for (int i = 0; i < 4; i++)
        aBase[i] = ((wm * 64 + i * 16 + aRow) * ASTR + aCol4) * 4;

    int tig = lane & 3, g = lane >> 2;
    int bCol = wn * 32 + g;              // + j*8 per n-frag

    float c[4][4][4];
#pragma unroll
    for (int i = 0; i < 4; i++)
#pragma unroll
        for (int j = 0; j < 4; j++)
#pragma unroll
            for (int r = 0; r < 4; r++) c[i][j][r] = 0.f;

    int ntiles = K >> 5;

    auto issue = [&](int t, int slot) {
        int k0 = t << 5;
#pragma unroll
        for (int it = 0; it < 4; it++) {       // A: 128 rows x 8 chunks
            int idx = tid + it * 256;
            int row = idx >> 3, ch = (idx & 7) * 4;
            const float* src = A + (size_t)(m0 + row) * K + k0 + ch;
            int ok = (m0 + row < M) ? 16 : 0;
            cp_async16(sA + (slot * A_TILE + row * ASTR + ch) * 4, src, ok);
        }
#pragma unroll
        for (int it = 0; it < 4; it++) {       // B: 32 rows x 32 chunks
            int idx = tid + it * 256;
            int row = idx >> 5, ch = (idx & 31) * 4;
            cp_async16(sB + (slot * B_TILE + row * BSTR + ch) * 4,
                       B + (size_t)(k0 + row) * N + n0 + ch, 16);
        }
        asm volatile("cp.async.commit_group;");
    };

    issue(0, 0);
    if (ntiles > 1) issue(1, 1);

    for (int t = 0; t < ntiles; t++) {
        int slot = t % NSTAGE;
        if (t + 1 < ntiles)
            asm volatile("cp.async.wait_group 1;");
        else
            asm volatile("cp.async.wait_group 0;");
        __syncthreads();
        if (t + 2 < ntiles) issue(t + 2, (t + 2) % NSTAGE);

        const float* Bp = Bs + slot * B_TILE;
        uint32_t sAb = sA + slot * A_TILE * 4;
#pragma unroll
        for (int kk = 0; kk < 32; kk += 8) {
            uint32_t a[4][4];
#pragma unroll
            for (int i = 0; i < 4; i++) {
                asm volatile("ldmatrix.sync.aligned.m8n8.x4.shared.b16 {%0,%1,%2,%3}, [%4];"
                             : "=r"(a[i][0]), "=r"(a[i][1]), "=r"(a[i][2]), "=r"(a[i][3])
                             : "r"(sAb + aBase[i] + kk * 4));
            }
            uint32_t b[4][2];
#pragma unroll
            for (int j = 0; j < 4; j++) {
                b[j][0] = __float_as_uint(Bp[(kk + tig) * BSTR + bCol + j * 8]);
                b[j][1] = __float_as_uint(Bp[(kk + 4 + tig) * BSTR + bCol + j * 8]);
            }
#pragma unroll
            for (int i = 0; i < 4; i++)
#pragma unroll
                for (int j = 0; j < 4; j++) {
                    asm volatile(
                        "mma.sync.aligned.m16n8k8.row.col.f32.tf32.tf32.f32 "
                        "{%0,%1,%2,%3}, {%4,%5,%6,%7}, {%8,%9}, {%0,%1,%2,%3};"
                        : "+f"(c[i][j][0]), "+f"(c[i][j][1]),
                          "+f"(c[i][j][2]), "+f"(c[i][j][3])
                        : "r"(a[i][0]), "r"(a[i][1]), "r"(a[i][2]), "r"(a[i][3]),
                          "r"(b[j][0]), "r"(b[j][1]));
                }
        }
    }

    // epilogue
#pragma unroll
    for (int i = 0; i < 4; i++) {
        int r0 = m0 + wm * 64 + i * 16 + g;
#pragma unroll
        for (int j = 0; j < 4; j++) {
            int col = n0 + wn * 32 + j * 8 + 2 * tig;
#pragma unroll
            for (int half = 0; half < 2; half++) {
                int m = r0 + half * 8;
                if (m >= M) continue;
                float v0 = c[i][j][2 * half + 0];
                float v1 = c[i][j][2 * half + 1];
                if (EPI == 1) {
                    v0 += R[(size_t)m * N + col];
                    v1 += R[(size_t)m * N + col + 1];
                } else if (EPI == 2) {
                    v0 += bias[col];
                    v1 += bias[col + 1];
                    v0 = 0.5f * v0 * (1.f + erff(v0 * 0.70710678118654752f));
                    v1 = 0.5f * v1 * (1.f + erff(v1 * 0.70710678118654752f));
                } else if (EPI == 3) {
                    v0 += bias[col] + R[(size_t)m * N + col];
                    v1 += bias[col + 1] + R[(size_t)m * N + col + 1];
                }
                *(float2*)(C + (size_t)m * N + col) = make_float2(v0, v1);
            }
        }
    }
}

// dot of two float4 accumulated into s (4 chained FMA)
__device__ __forceinline__ float dot4(float s, float4 a, float4 b) {
    s += a.x * b.x; s += a.y * b.y; s += a.z * b.z; s += a.w * b.w;
    return s;
}

// ---------------- temporal attention: single-pass, 8-way ILP dot ------------
__global__ void __launch_bounds__(256) attn_temporal() {
    extern __shared__ float4 sm4[];
    float4* K4 = sm4;               // NT*16 float4
    float4* V4 = sm4 + NT * 16;

    int b = blockIdx.x >> 3, h = blockIdx.x & 7;
    const float* base = g_QKV1 + (size_t)b * NT * (3 * DIMX);

    for (int i = threadIdx.x; i < NT * 16; i += 256) {
        int t = i >> 4, d4 = i & 15;
        K4[i] = *(const float4*)(base + (size_t)t * 1536 + DIMX + h * DH + d4 * 4);
        V4[i] = *(const float4*)(base + (size_t)t * 1536 + 2 * DIMX + h * DH + d4 * 4);
    }
    __syncthreads();

    for (int q = threadIdx.x; q < NT; q += 256) {
        float4 qr[16];
        const float4* qp = (const float4*)(base + (size_t)q * 1536 + h * DH);
#pragma unroll
        for (int i = 0; i < 16; i++) {
            float4 v = qp[i];
            v.x *= 0.125f; v.y *= 0.125f; v.z *= 0.125f; v.w *= 0.125f;
            qr[i] = v;
        }
        float4 o[16];
#pragma unroll
        for (int i = 0; i < 16; i++) o[i] = make_float4(0.f, 0.f, 0.f, 0.f);
        float sum = 0.f;
        for (int t = 0; t < NT; t++) {
            float p0 = 0.f, p1 = 0.f, p2 = 0.f, p3 = 0.f;
            float p4 = 0.f, p5 = 0.f, p6 = 0.f, p7 = 0.f;
#pragma unroll
            for (int i = 0; i < 16; i += 8) {
                p0 = dot4(p0, qr[i + 0], K4[t * 16 + i + 0]);
                p1 = dot4(p1, qr[i + 1], K4[t * 16 + i + 1]);
                p2 = dot4(p2, qr[i + 2], K4[t * 16 + i + 2]);
                p3 = dot4(p3, qr[i + 3], K4[t * 16 + i + 3]);
                p4 = dot4(p4, qr[i + 4], K4[t * 16 + i + 4]);
                p5 = dot4(p5, qr[i + 5], K4[t * 16 + i + 5]);
                p6 = dot4(p6, qr[i + 6], K4[t * 16 + i + 6]);
                p7 = dot4(p7, qr[i + 7], K4[t * 16 + i + 7]);
            }
            float acc = ((p0 + p1) + (p2 + p3)) + ((p4 + p5) + (p6 + p7));
            float e = __expf(acc);
            sum += e;
#pragma unroll
            for (int i = 0; i < 16; i++) {
                float4 vv = V4[t * 16 + i];
                o[i].x += e * vv.x; o[i].y += e * vv.y;
                o[i].z += e * vv.z; o[i].w += e * vv.w;
            }
        }
        float inv = 1.f / sum;
        float4* op = (float4*)(g_O1 + ((size_t)b * NT + q) * DIMX + h * DH);
#pragma unroll
        for (int i = 0; i < 16; i++) {
            o[i].x *= inv; o[i].y *= inv; o[i].z *= inv; o[i].w *= inv;
            op[i] = o[i];
        }
    }
}

// ---------------- Linformer E projection ------------------------------------
__global__ void eproj(const float* __restrict__ E) {
    __shared__ float Ks[NS * DH];
    __shared__ float Vs[NS * DH];
    int blk = blockIdx.x;           // fb*8 + h
    int fb = blk >> 3, h = blk & 7;
    const float* base = g_QKV2 + (size_t)fb * NS * 1536;
    for (int i = threadIdx.x; i < NS * DH; i += blockDim.x) {
        int j = i >> 6, d = i & 63;
        Ks[i] = base[(size_t)j * 1536 + DIMX + h * DH + d];
        Vs[i] = base[(size_t)j * 1536 + 2 * DIMX + h * DH + d];
    }
    __syncthreads();
    int d = threadIdx.x & 63;
    for (int kk = threadIdx.x >> 6; kk < KPROJ; kk += 4) {
        float ak0 = 0.f, ak1 = 0.f, av0 = 0.f, av1 = 0.f;
#pragma unroll 8
        for (int j = 0; j < 64; j += 2) {
            float e0 = E[j * KPROJ + kk];
            float e1 = E[(j + 1) * KPROJ + kk];
            ak0 += e0 * Ks[j * DH + d];
            ak1 += e1 * Ks[(j + 1) * DH + d];
            av0 += e0 * Vs[j * DH + d];
            av1 += e1 * Vs[(j + 1) * DH + d];
        }
        float e64 = E[64 * KPROJ + kk];
        float ak = ak0 + ak1 + e64 * Ks[64 * DH + d];
        float av = av0 + av1 + e64 * Vs[64 * DH + d];
        size_t o = ((size_t)blk * KPROJ + kk) * DH + d;
        g_KE[o] = ak;
        g_VE[o] = av;
    }
}

// ---------------- spatial (Linformer) attention: single-pass, 8-way ILP -----
__global__ void __launch_bounds__(96) attn_spatial() {
    extern __shared__ float4 sm4[];
    float4* K4 = sm4;               // KPROJ*16
    float4* V4 = sm4 + KPROJ * 16;
    int blk = blockIdx.x;           // fb*8 + h
    const float4* kb = (const float4*)(g_KE + (size_t)blk * KPROJ * DH);
    const float4* vb = (const float4*)(g_VE + (size_t)blk * KPROJ * DH);
    for (int i = threadIdx.x; i < KPROJ * 16; i += 96) {
        K4[i] = kb[i];
        V4[i] = vb[i];
    }
    __syncthreads();

    int fb = blk >> 3, h = blk & 7;
    int q = threadIdx.x;
    if (q < NS) {
        const float4* qp = (const float4*)(g_QKV2 + ((size_t)fb * NS + q) * 1536 + h * DH);
        float4 qr[16];
#pragma unroll
        for (int i = 0; i < 16; i++) {
            float4 v = qp[i];
            v.x *= 0.125f; v.y *= 0.125f; v.z *= 0.125f; v.w *= 0.125f;
            qr[i] = v;
        }
        float4 o[16];
#pragma unroll
        for (int i = 0; i < 16; i++) o[i] = make_float4(0.f, 0.f, 0.f, 0.f);
        float sum = 0.f;
        for (int t = 0; t < KPROJ; t++) {
            float p0 = 0.f, p1 = 0.f, p2 = 0.f, p3 = 0.f;
            float p4 = 0.f, p5 = 0.f, p6 = 0.f, p7 = 0.f;
#pragma unroll
            for (int i = 0; i < 16; i += 8) {
                p0 = dot4(p0, qr[i + 0], K4[t * 16 + i + 0]);
                p1 = dot4(p1, qr[i + 1], K4[t * 16 + i + 1]);
                p2 = dot4(p2, qr[i + 2], K4[t * 16 + i + 2]);
                p3 = dot4(p3, qr[i + 3], K4[t * 16 + i + 3]);
                p4 = dot4(p4, qr[i + 4], K4[t * 16 + i + 4]);
                p5 = dot4(p5, qr[i + 5], K4[t * 16 + i + 5]);
                p6 = dot4(p6, qr[i + 6], K4[t * 16 + i + 6]);
                p7 = dot4(p7, qr[i + 7], K4[t * 16 + i + 7]);
            }
            float acc = ((p0 + p1) + (p2 + p3)) + ((p4 + p5) + (p6 + p7));
            float e = __expf(acc);
            sum += e;
#pragma unroll
            for (int i = 0; i < 16; i++) {
                float4 vv = V4[t * 16 + i];
                o[i].x += e * vv.x; o[i].y += e * vv.y;
                o[i].z += e * vv.z; o[i].w += e * vv.w;
            }
        }
        float inv = 1.f / sum;
        float4* op = (float4*)(g_O2 + ((size_t)fb * NS + q) * DIMX + h * DH);
#pragma unroll
        for (int i = 0; i < 16; i++) {
            o[i].x *= inv; o[i].y *= inv; o[i].z *= inv; o[i].w *= inv;
            op[i] = o[i];
        }
    }
}

// ---------------- launch -----------------------------------------------------
extern "C" void kernel_launch(void* const* d_in, const int* in_sizes, int n_in,
                              void* d_out, int out_size) {
    const float* x      = (const float*)d_in[0];
    const float* Wqkv_t = (const float*)d_in[1];
    const float* Wo_t   = (const float*)d_in[2];
    const float* Wqkv_s = (const float*)d_in[3];
    const float* Wo_s   = (const float*)d_in[4];
    const float* E      = (const float*)d_in[5];
    const float* W1     = (const float*)d_in[6];
    const float* b1     = (const float*)d_in[7];
    const float* W2     = (const float*)d_in[8];
    const float* b2     = (const float*)d_in[9];
    float* out = (float*)d_out;
    (void)in_sizes; (void)n_in; (void)out_size;

    float *X1, *QKV1, *O1, *Y1, *X2, *QKV2, *O2, *Y2, *H;
    cudaGetSymbolAddress((void**)&X1, g_X1);
    cudaGetSymbolAddress((void**)&QKV1, g_QKV1);
    cudaGetSymbolAddress((void**)&O1, g_O1);
    cudaGetSymbolAddress((void**)&Y1, g_Y1);
    cudaGetSymbolAddress((void**)&X2, g_X2);
    cudaGetSymbolAddress((void**)&QKV2, g_QKV2);
    cudaGetSymbolAddress((void**)&O2, g_O2);
    cudaGetSymbolAddress((void**)&Y2, g_Y2);
    cudaGetSymbolAddress((void**)&H, g_H);

    const int SMEM_T = 2 * NT * DH * 4;      // 131584 B
    const int SMEM_S = 2 * KPROJ * DH * 4;   // 65536 B
    cudaFuncSetAttribute(attn_temporal, cudaFuncAttributeMaxDynamicSharedMemorySize, SMEM_T);
    cudaFuncSetAttribute(attn_spatial, cudaFuncAttributeMaxDynamicSharedMemorySize, SMEM_S);
    cudaFuncSetAttribute(tf32_gemm<0>, cudaFuncAttributeMaxDynamicSharedMemorySize, GEMM_SMEM);
    cudaFuncSetAttribute(tf32_gemm<1>, cudaFuncAttributeMaxDynamicSharedMemorySize, GEMM_SMEM);
    cudaFuncSetAttribute(tf32_gemm<2>, cudaFuncAttributeMaxDynamicSharedMemorySize, GEMM_SMEM);
    cudaFuncSetAttribute(tf32_gemm<3>, cudaFuncAttributeMaxDynamicSharedMemorySize, GEMM_SMEM);

    // ---- temporal stage ----
    gather_temporal<<<(MT * DIMX + 255) / 256, 256>>>(x);
    tf32_gemm<0><<<dim3(3 * DIMX / 128, (MT + 127) / 128), 256, GEMM_SMEM>>>(
        X1, Wqkv_t, QKV1, nullptr, nullptr, MT, 3 * DIMX, DIMX);
    attn_temporal<<<PATCHES * HEADS, 256, SMEM_T>>>();
    tf32_gemm<1><<<dim3(DIMX / 128, (MT + 127) / 128), 256, GEMM_SMEM>>>(
        O1, Wo_t, Y1, nullptr, X1, MT, DIMX, DIMX);

    // ---- spatial stage ----
    gather_spatial<<<(MS * DIMX + 255) / 256, 256>>>();
    tf32_gemm<0><<<dim3(3 * DIMX / 128, MS / 128), 256, GEMM_SMEM>>>(
        X2, Wqkv_s, QKV2, nullptr, nullptr, MS, 3 * DIMX, DIMX);
    eproj<<<FRAMES * HEADS, 256>>>(E);
    attn_spatial<<<FRAMES * HEADS, 96, SMEM_S>>>();
    tf32_gemm<1><<<dim3(DIMX / 128, MS / 128), 256, GEMM_SMEM>>>(
        O2, Wo_s, Y2, nullptr, X2, MS, DIMX, DIMX);

    // ---- FFN ----
    tf32_gemm<2><<<dim3(DFF / 128, MS / 128), 256, GEMM_SMEM>>>(
        Y2, W1, H, b1, nullptr, MS, DFF, DIMX);
    tf32_gemm<3><<<dim3(DIMX / 128, MS / 128), 256, GEMM_SMEM>>>(
        H, W2, out, b2, Y2, MS, DIMX, DFF);
}

// round 7
// speedup vs baseline: 1.3647x; 1.3647x over previous
#include <cuda_runtime.h>
#include <math.h>
#include <cstdint>

#define FRAMES 256
#define PATCHES 64
#define DIMX 512
#define HEADS 8
#define DH 64
#define DFF 1024
#define KPROJ 128
#define NT 257              // temporal seq len (cls + 256 frames)
#define NS 65               // spatial seq len (cls + 64 patches)
#define MT (PATCHES * NT)   // 16448 rows temporal
#define MS (FRAMES * NS)    // 16640 rows spatial

// ---------------- scratch (device globals; no allocation allowed) ----------
__device__ float g_X1[MT * DIMX];
__device__ float g_QKV1[MT * 3 * DIMX];
__device__ float g_O1[MT * DIMX];
__device__ float g_Y1[MT * DIMX];
__device__ float g_X2[MS * DIMX];
__device__ float g_QKV2[MS * 3 * DIMX];
__device__ float g_KE[FRAMES * HEADS * KPROJ * DH];
__device__ float g_VE[FRAMES * HEADS * KPROJ * DH];
__device__ float g_O2[MS * DIMX];
__device__ float g_Y2[MS * DIMX];
__device__ float g_H[MS * DFF];

// ---------------- gathers ---------------------------------------------------
__global__ void gather_temporal(const float* __restrict__ x) {
    int idx = blockIdx.x * blockDim.x + threadIdx.x;
    if (idx >= MT * DIMX) return;
    int d = idx & (DIMX - 1);
    int row = idx >> 9;
    int t = row % NT;
    int pb = row / NT;
    int src = (t == 0) ? 0 : (1 + (t - 1) * PATCHES + pb);
    g_X1[idx] = x[(size_t)src * DIMX + d];
}

__global__ void gather_spatial() {
    int idx = blockIdx.x * blockDim.x + threadIdx.x;
    if (idx >= MS * DIMX) return;
    int d = idx & (DIMX - 1);
    int row = idx >> 9;
    int s = row % NS;
    int fb = row / NS;
    int srow = (s == 0) ? ((fb & 63) * NT) : ((s - 1) * NT + 1 + fb);
    g_X2[idx] = g_Y1[(size_t)srow * DIMX + d];
}

// ---------------- tf32 tensor-core GEMM (round-4 best config) ---------------
#define ASTR 36
#define BSTR 136
#define A_TILE (128 * ASTR)
#define B_TILE (32 * BSTR)
#define GEMM_SMEM ((2 * A_TILE + 2 * B_TILE) * 4)

__device__ __forceinline__ void cp_async16(uint32_t dst, const float* src, int srcsize) {
    asm volatile("cp.async.cg.shared.global [%0], [%1], 16, %2;\n"
                 :: "r"(dst), "l"(src), "r"(srcsize));
}

template <int EPI>
__global__ void __launch_bounds__(256)
tf32_gemm(const float* __restrict__ A, const float* __restrict__ B,
          float* __restrict__ C, const float* __restrict__ bias,
          const float* __restrict__ R, int M, int N, int K) {
    extern __shared__ float smem[];
    float* As = smem;                    // [2][128][ASTR]
    float* Bs = smem + 2 * A_TILE;       // [2][32][BSTR]
    uint32_t sA = (uint32_t)__cvta_generic_to_shared(As);
    uint32_t sB = (uint32_t)__cvta_generic_to_shared(Bs);

    int tid = threadIdx.x;
    int lane = tid & 31, warp = tid >> 5;
    int wm = warp & 1, wn = warp >> 1;
    int m0 = blockIdx.y * 128;
    int n0 = blockIdx.x * 128;

    int aRow = lane & 15;
    int aCol4 = (lane >> 4) * 4;
    uint32_t aBase[4];
#pragma unroll
    for (int i = 0; i < 4; i++)
        aBase[i] = ((wm * 64 + i * 16 + aRow) * ASTR + aCol4) * 4;

    int tig = lane & 3, g = lane >> 2;
    int bCol = wn * 32 + g;

    float c[4][4][4];
#pragma unroll
    for (int i = 0; i < 4; i++)
#pragma unroll
        for (int j = 0; j < 4; j++)
#pragma unroll
            for (int r = 0; r < 4; r++) c[i][j][r] = 0.f;

    int ntiles = K >> 5;

    auto issue = [&](int t, int buf) {
        int k0 = t << 5;
#pragma unroll
        for (int it = 0; it < 4; it++) {
            int idx = tid + it * 256;
            int row = idx >> 3, ch = (idx & 7) * 4;
            const float* src = A + (size_t)(m0 + row) * K + k0 + ch;
            int ok = (m0 + row < M) ? 16 : 0;
            cp_async16(sA + (buf * A_TILE + row * ASTR + ch) * 4, src, ok);
        }
#pragma unroll
        for (int it = 0; it < 4; it++) {
            int idx = tid + it * 256;
            int row = idx >> 5, ch = (idx & 31) * 4;
            cp_async16(sB + (buf * B_TILE + row * BSTR + ch) * 4,
                       B + (size_t)(k0 + row) * N + n0 + ch, 16);
        }
        asm volatile("cp.async.commit_group;");
    };

    issue(0, 0);

    for (int t = 0; t < ntiles; t++) {
        int buf = t & 1;
        if (t + 1 < ntiles) {
            issue(t + 1, (t + 1) & 1);
            asm volatile("cp.async.wait_group 1;");
        } else {
            asm volatile("cp.async.wait_group 0;");
        }
        __syncthreads();

        const float* Bp = Bs + buf * B_TILE;
        uint32_t sAb = sA + buf * A_TILE * 4;
#pragma unroll
        for (int kk = 0; kk < 32; kk += 8) {
            uint32_t a[4][4];
#pragma unroll
            for (int i = 0; i < 4; i++) {
                asm volatile("ldmatrix.sync.aligned.m8n8.x4.shared.b16 {%0,%1,%2,%3}, [%4];"
                             : "=r"(a[i][0]), "=r"(a[i][1]), "=r"(a[i][2]), "=r"(a[i][3])
                             : "r"(sAb + aBase[i] + kk * 4));
            }
            uint32_t b[4][2];
#pragma unroll
            for (int j = 0; j < 4; j++) {
                b[j][0] = __float_as_uint(Bp[(kk + tig) * BSTR + bCol + j * 8]);
                b[j][1] = __float_as_uint(Bp[(kk + 4 + tig) * BSTR + bCol + j * 8]);
            }
#pragma unroll
            for (int i = 0; i < 4; i++)
#pragma unroll
                for (int j = 0; j < 4; j++) {
                    asm volatile(
                        "mma.sync.aligned.m16n8k8.row.col.f32.tf32.tf32.f32 "
                        "{%0,%1,%2,%3}, {%4,%5,%6,%7}, {%8,%9}, {%0,%1,%2,%3};"
                        : "+f"(c[i][j][0]), "+f"(c[i][j][1]),
                          "+f"(c[i][j][2]), "+f"(c[i][j][3])
                        : "r"(a[i][0]), "r"(a[i][1]), "r"(a[i][2]), "r"(a[i][3]),
                          "r"(b[j][0]), "r"(b[j][1]));
                }
        }
        __syncthreads();
    }

#pragma unroll
    for (int i = 0; i < 4; i++) {
        int r0 = m0 + wm * 64 + i * 16 + g;
#pragma unroll
        for (int j = 0; j < 4; j++) {
            int col = n0 + wn * 32 + j * 8 + 2 * tig;
#pragma unroll
            for (int half = 0; half < 2; half++) {
                int m = r0 + half * 8;
                if (m >= M) continue;
                float v0 = c[i][j][2 * half + 0];
                float v1 = c[i][j][2 * half + 1];
                if (EPI == 1) {
                    v0 += R[(size_t)m * N + col];
                    v1 += R[(size_t)m * N + col + 1];
                } else if (EPI == 2) {
                    v0 += bias[col];
                    v1 += bias[col + 1];
                    v0 = 0.5f * v0 * (1.f + erff(v0 * 0.70710678118654752f));
                    v1 = 0.5f * v1 * (1.f + erff(v1 * 0.70710678118654752f));
                } else if (EPI == 3) {
                    v0 += bias[col] + R[(size_t)m * N + col];
                    v1 += bias[col + 1] + R[(size_t)m * N + col + 1];
                }
                *(float2*)(C + (size_t)m * N + col) = make_float2(v0, v1);
            }
        }
    }
}

// ---------------- tensor-core attention --------------------------------------
// Per block: one (batch, head). K/V staged in smem; S = Q K^T via mma.tf32,
// exp in regs (masked on padded keys), P staged per-warp in smem, O += P V via mma.
#define KSTR 68    // K smem row stride: QK B-loads hit 32 distinct banks (4g+tig)
#define VSTR 72    // V smem row stride: PV B-loads hit 32 distinct banks (8tig+g)
#define PSTR 68
#define TKPAD 272  // temporal keys padded to 17*16
#define SMEM_AT ((TKPAD * KSTR + TKPAD * VSTR + 8 * 16 * PSTR) * 4)   // 187136 B
#define SMEM_AS ((KPROJ * KSTR + KPROJ * VSTR + 8 * 16 * PSTR) * 4)   // 106496 B

__device__ __forceinline__ void mma8(float (&c)[4], const float (&a)[4],
                                     uint32_t b0, uint32_t b1) {
    asm volatile(
        "mma.sync.aligned.m16n8k8.row.col.f32.tf32.tf32.f32 "
        "{%0,%1,%2,%3}, {%4,%5,%6,%7}, {%8,%9}, {%0,%1,%2,%3};"
        : "+f"(c[0]), "+f"(c[1]), "+f"(c[2]), "+f"(c[3])
        : "r"(__float_as_uint(a[0])), "r"(__float_as_uint(a[1])),
          "r"(__float_as_uint(a[2])), "r"(__float_as_uint(a[3])),
          "r"(b0), "r"(b1));
}

// One key-block of NTILE*8 keys: S-mma, masked exp, P->smem, PV-mma.
template <int NTILE>
__device__ __forceinline__ void attn_kblock(
    const float* __restrict__ Ksb, const float* __restrict__ Vsb,
    float* __restrict__ Pw,
    const float (&qa)[8][4], float (&oc)[8][4],
    float& sum0, float& sum1,
    int g, int tig, int keybase, int klimit)
{
    float sc[NTILE][4];
#pragma unroll
    for (int nt = 0; nt < NTILE; nt++) {
        sc[nt][0] = sc[nt][1] = sc[nt][2] = sc[nt][3] = 0.f;
        const float* Kp = Ksb + (nt * 8 + g) * KSTR;
#pragma unroll
        for (int kk = 0; kk < 8; kk++) {
            uint32_t b0 = __float_as_uint(Kp[kk * 8 + tig]);
            uint32_t b1 = __float_as_uint(Kp[kk * 8 + tig + 4]);
            mma8(sc[nt], qa[kk], b0, b1);
        }
    }
#pragma unroll
    for (int nt = 0; nt < NTILE; nt++) {
        int key = keybase + nt * 8 + 2 * tig;
        float e0 = (key     < klimit) ? __expf(sc[nt][0]) : 0.f;
        float e1 = (key + 1 < klimit) ? __expf(sc[nt][1]) : 0.f;
        float e2 = (key     < klimit) ? __expf(sc[nt][2]) : 0.f;
        float e3 = (key + 1 < klimit) ? __expf(sc[nt][3]) : 0.f;
        sum0 += e0 + e1;
        sum1 += e2 + e3;
        *(float2*)(Pw + g * PSTR + nt * 8 + 2 * tig)       = make_float2(e0, e1);
        *(float2*)(Pw + (g + 8) * PSTR + nt * 8 + 2 * tig) = make_float2(e2, e3);
    }
    __syncwarp();
    float pa[NTILE][4];
#pragma unroll
    for (int kc = 0; kc < NTILE; kc++) {
        pa[kc][0] = Pw[g * PSTR + kc * 8 + tig];
        pa[kc][1] = Pw[(g + 8) * PSTR + kc * 8 + tig];
        pa[kc][2] = Pw[g * PSTR + kc * 8 + tig + 4];
        pa[kc][3] = Pw[(g + 8) * PSTR + kc * 8 + tig + 4];
    }
#pragma unroll
    for (int nt = 0; nt < 8; nt++) {
#pragma unroll
        for (int kc = 0; kc < NTILE; kc++) {
            const float* Vp = Vsb + (kc * 8 + tig) * VSTR + nt * 8 + g;
            uint32_t b0 = __float_as_uint(Vp[0]);
            uint32_t b1 = __float_as_uint(Vp[4 * VSTR]);
            mma8(oc[nt], pa[kc], b0, b1);
        }
    }
    __syncwarp();
}

// ---------------- temporal attention (mma) -----------------------------------
__global__ void __launch_bounds__(256) attn_t_mma() {
    extern __shared__ float sm[];
    float* Ks = sm;
    float* Vs = Ks + TKPAD * KSTR;
    float* Ps = Vs + TKPAD * VSTR;

    int b = blockIdx.x >> 3, h = blockIdx.x & 7;
    const float* base = g_QKV1 + (size_t)b * NT * 1536;

    for (int i = threadIdx.x; i < TKPAD * 16; i += 256) {
        int t = i >> 4, c4 = (i & 15) * 4;
        float4 kv = make_float4(0.f, 0.f, 0.f, 0.f);
        float4 vv = make_float4(0.f, 0.f, 0.f, 0.f);
        if (t < NT) {
            kv = *(const float4*)(base + (size_t)t * 1536 + 512 + h * 64 + c4);
            vv = *(const float4*)(base + (size_t)t * 1536 + 1024 + h * 64 + c4);
        }
        float* kd = Ks + t * KSTR + c4;
        kd[0] = kv.x; kd[1] = kv.y; kd[2] = kv.z; kd[3] = kv.w;
        float* vd = Vs + t * VSTR + c4;
        vd[0] = vv.x; vd[1] = vv.y; vd[2] = vv.z; vd[3] = vv.w;
    }
    __syncthreads();

    int lane = threadIdx.x & 31, warp = threadIdx.x >> 5;
    int g = lane >> 2, tig = lane & 3;
    float* Pw = Ps + warp * 16 * PSTR;

    for (int qt = warp; qt < 17; qt += 8) {
        int q0 = qt * 16;
        int r0 = min(q0 + g, NT - 1), r1 = min(q0 + g + 8, NT - 1);
        const float* Q0 = base + (size_t)r0 * 1536 + h * 64;
        const float* Q1 = base + (size_t)r1 * 1536 + h * 64;
        float qa[8][4];
#pragma unroll
        for (int kk = 0; kk < 8; kk++) {
            qa[kk][0] = Q0[kk * 8 + tig] * 0.125f;
            qa[kk][1] = Q1[kk * 8 + tig] * 0.125f;
            qa[kk][2] = Q0[kk * 8 + tig + 4] * 0.125f;
            qa[kk][3] = Q1[kk * 8 + tig + 4] * 0.125f;
        }
        float oc[8][4];
#pragma unroll
        for (int nt = 0; nt < 8; nt++)
            oc[nt][0] = oc[nt][1] = oc[nt][2] = oc[nt][3] = 0.f;
        float sum0 = 0.f, sum1 = 0.f;

#pragma unroll
        for (int kb = 0; kb < 4; kb++)
            attn_kblock<8>(Ks + kb * 64 * KSTR, Vs + kb * 64 * VSTR, Pw,
                           qa, oc, sum0, sum1, g, tig, kb * 64, NT);
        attn_kblock<2>(Ks + 256 * KSTR, Vs + 256 * VSTR, Pw,
                       qa, oc, sum0, sum1, g, tig, 256, NT);

        sum0 += __shfl_xor_sync(0xffffffffu, sum0, 1);
        sum0 += __shfl_xor_sync(0xffffffffu, sum0, 2);
        sum1 += __shfl_xor_sync(0xffffffffu, sum1, 1);
        sum1 += __shfl_xor_sync(0xffffffffu, sum1, 2);
        float inv0 = 1.f / sum0, inv1 = 1.f / sum1;

        int row0 = q0 + g, row1 = q0 + g + 8;
        if (row0 < NT) {
            float* op = g_O1 + ((size_t)b * NT + row0) * 512 + h * 64;
#pragma unroll
            for (int nt = 0; nt < 8; nt++)
                *(float2*)(op + nt * 8 + 2 * tig) =
                    make_float2(oc[nt][0] * inv0, oc[nt][1] * inv0);
        }
        if (row1 < NT) {
            float* op = g_O1 + ((size_t)b * NT + row1) * 512 + h * 64;
#pragma unroll
            for (int nt = 0; nt < 8; nt++)
                *(float2*)(op + nt * 8 + 2 * tig) =
                    make_float2(oc[nt][2] * inv1, oc[nt][3] * inv1);
        }
    }
}

// ---------------- spatial (Linformer) attention (mma) ------------------------
__global__ void __launch_bounds__(256) attn_s_mma() {
    extern __shared__ float sm[];
    float* Ks = sm;
    float* Vs = Ks + KPROJ * KSTR;
    float* Ps = Vs + KPROJ * VSTR;

    int blk = blockIdx.x;           // fb*8 + h
    int fb = blk >> 3, h = blk & 7;
    const float* kesrc = g_KE + (size_t)blk * KPROJ * DH;
    const float* vesrc = g_VE + (size_t)blk * KPROJ * DH;

    for (int i = threadIdx.x; i < KPROJ * 16; i += 256) {
        int t = i >> 4, c4 = (i & 15) * 4;
        float4 kv = *(const float4*)(kesrc + t * 64 + c4);
        float4 vv = *(const float4*)(vesrc + t * 64 + c4);
        float* kd = Ks + t * KSTR + c4;
        kd[0] = kv.x; kd[1] = kv.y; kd[2] = kv.z; kd[3] = kv.w;
        float* vd = Vs + t * VSTR + c4;
        vd[0] = vv.x; vd[1] = vv.y; vd[2] = vv.z; vd[3] = vv.w;
    }
    __syncthreads();

    int lane = threadIdx.x & 31, warp = threadIdx.x >> 5;
    int g = lane >> 2, tig = lane & 3;
    float* Pw = Ps + warp * 16 * PSTR;

    for (int qt = warp; qt < 5; qt += 8) {
        int q0 = qt * 16;
        int r0 = min(q0 + g, NS - 1), r1 = min(q0 + g + 8, NS - 1);
        const float* Q0 = g_QKV2 + ((size_t)fb * NS + r0) * 1536 + h * 64;
        const float* Q1 = g_QKV2 + ((size_t)fb * NS + r1) * 1536 + h * 64;
        float qa[8][4];
#pragma unroll
        for (int kk = 0; kk < 8; kk++) {
            qa[kk][0] = Q0[kk * 8 + tig] * 0.125f;
            qa[kk][1] = Q1[kk * 8 + tig] * 0.125f;
            qa[kk][2] = Q0[kk * 8 + tig + 4] * 0.125f;
            qa[kk][3] = Q1[kk * 8 + tig + 4] * 0.125f;
        }
        float oc[8][4];
#pragma unroll
        for (int nt = 0; nt < 8; nt++)
            oc[nt][0] = oc[nt][1] = oc[nt][2] = oc[nt][3] = 0.f;
        float sum0 = 0.f, sum1 = 0.f;

        attn_kblock<8>(Ks, Vs, Pw, qa, oc, sum0, sum1, g, tig, 0, KPROJ);
        attn_kblock<8>(Ks + 64 * KSTR, Vs + 64 * VSTR, Pw,
                       qa, oc, sum0, sum1, g, tig, 64, KPROJ);

        sum0 += __shfl_xor_sync(0xffffffffu, sum0, 1);
        sum0 += __shfl_xor_sync(0xffffffffu, sum0, 2);
        sum1 += __shfl_xor_sync(0xffffffffu, sum1, 1);
        sum1 += __shfl_xor_sync(0xffffffffu, sum1, 2);
        float inv0 = 1.f / sum0, inv1 = 1.f / sum1;

        int row0 = q0 + g, row1 = q0 + g + 8;
        if (row0 < NS) {
            float* op = g_O2 + ((size_t)fb * NS + row0) * 512 + h * 64;
#pragma unroll
            for (int nt = 0; nt < 8; nt++)
                *(float2*)(op + nt * 8 + 2 * tig) =
                    make_float2(oc[nt][0] * inv0, oc[nt][1] * inv0);
        }
        if (row1 < NS) {
            float* op = g_O2 + ((size_t)fb * NS + row1) * 512 + h * 64;
#pragma unroll
            for (int nt = 0; nt < 8; nt++)
                *(float2*)(op + nt * 8 + 2 * tig) =
                    make_float2(oc[nt][2] * inv1, oc[nt][3] * inv1);
        }
    }
}

// ---------------- Linformer E projection ------------------------------------
__global__ void eproj(const float* __restrict__ E) {
    __shared__ float Ks[NS * DH];
    __shared__ float Vs[NS * DH];
    int blk = blockIdx.x;           // fb*8 + h
    int fb = blk >> 3, h = blk & 7;
    const float* base = g_QKV2 + (size_t)fb * NS * 1536;
    for (int i = threadIdx.x; i < NS * DH; i += blockDim.x) {
        int j = i >> 6, d = i & 63;
        Ks[i] = base[(size_t)j * 1536 + DIMX + h * DH + d];
        Vs[i] = base[(size_t)j * 1536 + 2 * DIMX + h * DH + d];
    }
    __syncthreads();
    int d = threadIdx.x & 63;
    for (int kk = threadIdx.x >> 6; kk < KPROJ; kk += 4) {
        float ak0 = 0.f, ak1 = 0.f, av0 = 0.f, av1 = 0.f;
#pragma unroll 8
        for (int j = 0; j < 64; j += 2) {
            float e0 = E[j * KPROJ + kk];
            float e1 = E[(j + 1) * KPROJ + kk];
            ak0 += e0 * Ks[j * DH + d];
            ak1 += e1 * Ks[(j + 1) * DH + d];
            av0 += e0 * Vs[j * DH + d];
            av1 += e1 * Vs[(j + 1) * DH + d];
        }
        float e64 = E[64 * KPROJ + kk];
        float ak = ak0 + ak1 + e64 * Ks[64 * DH + d];
        float av = av0 + av1 + e64 * Vs[64 * DH + d];
        size_t o = ((size_t)blk * KPROJ + kk) * DH + d;
        g_KE[o] = ak;
        g_VE[o] = av;
    }
}

// ---------------- launch -----------------------------------------------------
extern "C" void kernel_launch(void* const* d_in, const int* in_sizes, int n_in,
                              void* d_out, int out_size) {
    const float* x      = (const float*)d_in[0];
    const float* Wqkv_t = (const float*)d_in[1];
    const float* Wo_t   = (const float*)d_in[2];
    const float* Wqkv_s = (const float*)d_in[3];
    const float* Wo_s   = (const float*)d_in[4];
    const float* E      = (const float*)d_in[5];
    const float* W1     = (const float*)d_in[6];
    const float* b1     = (const float*)d_in[7];
    const float* W2     = (const float*)d_in[8];
    const float* b2     = (const float*)d_in[9];
    float* out = (float*)d_out;
    (void)in_sizes; (void)n_in; (void)out_size;

    float *X1, *QKV1, *O1, *Y1, *X2, *QKV2, *O2, *Y2, *H;
    cudaGetSymbolAddress((void**)&X1, g_X1);
    cudaGetSymbolAddress((void**)&QKV1, g_QKV1);
    cudaGetSymbolAddress((void**)&O1, g_O1);
    cudaGetSymbolAddress((void**)&Y1, g_Y1);
    cudaGetSymbolAddress((void**)&X2, g_X2);
    cudaGetSymbolAddress((void**)&QKV2, g_QKV2);
    cudaGetSymbolAddress((void**)&O2, g_O2);
    cudaGetSymbolAddress((void**)&Y2, g_Y2);
    cudaGetSymbolAddress((void**)&H, g_H);

    cudaFuncSetAttribute(attn_t_mma, cudaFuncAttributeMaxDynamicSharedMemorySize, SMEM_AT);
    cudaFuncSetAttribute(attn_s_mma, cudaFuncAttributeMaxDynamicSharedMemorySize, SMEM_AS);
    cudaFuncSetAttribute(tf32_gemm<0>, cudaFuncAttributeMaxDynamicSharedMemorySize, GEMM_SMEM);
    cudaFuncSetAttribute(tf32_gemm<1>, cudaFuncAttributeMaxDynamicSharedMemorySize, GEMM_SMEM);
    cudaFuncSetAttribute(tf32_gemm<2>, cudaFuncAttributeMaxDynamicSharedMemorySize, GEMM_SMEM);
    cudaFuncSetAttribute(tf32_gemm<3>, cudaFuncAttributeMaxDynamicSharedMemorySize, GEMM_SMEM);

    // ---- temporal stage ----
    gather_temporal<<<(MT * DIMX + 255) / 256, 256>>>(x);
    tf32_gemm<0><<<dim3(3 * DIMX / 128, (MT + 127) / 128), 256, GEMM_SMEM>>>(
        X1, Wqkv_t, QKV1, nullptr, nullptr, MT, 3 * DIMX, DIMX);
    attn_t_mma<<<PATCHES * HEADS, 256, SMEM_AT>>>();
    tf32_gemm<1><<<dim3(DIMX / 128, (MT + 127) / 128), 256, GEMM_SMEM>>>(
        O1, Wo_t, Y1, nullptr, X1, MT, DIMX, DIMX);

    // ---- spatial stage ----
    gather_spatial<<<(MS * DIMX + 255) / 256, 256>>>();
    tf32_gemm<0><<<dim3(3 * DIMX / 128, MS / 128), 256, GEMM_SMEM>>>(
        X2, Wqkv_s, QKV2, nullptr, nullptr, MS, 3 * DIMX, DIMX);
    eproj<<<FRAMES * HEADS, 256>>>(E);
    attn_s_mma<<<FRAMES * HEADS, 256, SMEM_AS>>>();
    tf32_gemm<1><<<dim3(DIMX / 128, MS / 128), 256, GEMM_SMEM>>>(
        O2, Wo_s, Y2, nullptr, X2, MS, DIMX, DIMX);

    // ---- FFN ----
    tf32_gemm<2><<<dim3(DFF / 128, MS / 128), 256, GEMM_SMEM>>>(
        Y2, W1, H, b1, nullptr, MS, DFF, DIMX);
    tf32_gemm<3><<<dim3(DIMX / 128, MS / 128), 256, GEMM_SMEM>>>(
        H, W2, out, b2, Y2, MS, DIMX, DFF);
}

// round 8
// speedup vs baseline: 1.9267x; 1.4118x over previous
#include <cuda_runtime.h>
#include <math.h>
#include <cstdint>

#define FRAMES 256
#define PATCHES 64
#define DIMX 512
#define HEADS 8
#define DH 64
#define DFF 1024
#define KPROJ 128
#define NT 257              // temporal seq len (cls + 256 frames)
#define NS 65               // spatial seq len (cls + 64 patches)
#define MT (PATCHES * NT)   // 16448 rows temporal
#define MS (FRAMES * NS)    // 16640 rows spatial

// ---------------- scratch (device globals; no allocation allowed) ----------
__device__ float g_QKV1[MT * 3 * DIMX];
__device__ float g_O1[MT * DIMX];
__device__ float g_Y1[MT * DIMX];
__device__ float g_QKV2[MS * 3 * DIMX];
__device__ float g_O2[MS * DIMX];
__device__ float g_Y2[MS * DIMX];
__device__ float g_H[MS * DFF];

// ---------------- row remaps (gathers folded into GEMM loads) ---------------
// RM 1: temporal gather over x; RM 2: spatial gather over Y1.
template <int RM>
__device__ __forceinline__ const float* arow(const float* base, int r) {
    if (RM == 1) {
        int t = r % NT, pb = r / NT;
        int src = (t == 0) ? 0 : (1 + (t - 1) * PATCHES + pb);
        return base + (size_t)src * DIMX;
    } else {
        int s = r % NS, fb = r / NS;
        int srow = (s == 0) ? ((fb & 63) * NT) : ((s - 1) * NT + 1 + fb);
        return base + (size_t)srow * DIMX;
    }
}

// ---------------- tf32 tensor-core GEMM (round-4 best config) ---------------
// RMA: A-row remap mode (0 none, 1 temporal-from-x, 2 spatial-from-Y1)
// RMR: residual-row remap mode
#define ASTR 36
#define BSTR 136
#define A_TILE (128 * ASTR)
#define B_TILE (32 * BSTR)
#define GEMM_SMEM ((2 * A_TILE + 2 * B_TILE) * 4)

__device__ __forceinline__ void cp_async16(uint32_t dst, const float* src, int srcsize) {
    asm volatile("cp.async.cg.shared.global [%0], [%1], 16, %2;\n"
                 :: "r"(dst), "l"(src), "r"(srcsize));
}

template <int EPI, int RMA, int RMR>
__global__ void __launch_bounds__(256)
tf32_gemm(const float* __restrict__ A, const float* __restrict__ B,
          float* __restrict__ C, const float* __restrict__ bias,
          const float* __restrict__ R, int M, int N, int K) {
    extern __shared__ float smem[];
    float* As = smem;                    // [2][128][ASTR]
    float* Bs = smem + 2 * A_TILE;       // [2][32][BSTR]
    uint32_t sA = (uint32_t)__cvta_generic_to_shared(As);
    uint32_t sB = (uint32_t)__cvta_generic_to_shared(Bs);

    int tid = threadIdx.x;
    int lane = tid & 31, warp = tid >> 5;
    int wm = warp & 1, wn = warp >> 1;
    int m0 = blockIdx.y * 128;
    int n0 = blockIdx.x * 128;

    int aRow = lane & 15;
    int aCol4 = (lane >> 4) * 4;
    uint32_t aBase[4];
#pragma unroll
    for (int i = 0; i < 4; i++)
        aBase[i] = ((wm * 64 + i * 16 + aRow) * ASTR + aCol4) * 4;

    int tig = lane & 3, g = lane >> 2;
    int bCol = wn * 32 + g;

    float c[4][4][4];
#pragma unroll
    for (int i = 0; i < 4; i++)
#pragma unroll
        for (int j = 0; j < 4; j++)
#pragma unroll
            for (int r = 0; r < 4; r++) c[i][j][r] = 0.f;

    int ntiles = K >> 5;

    auto issue = [&](int t, int buf) {
        int k0 = t << 5;
#pragma unroll
        for (int it = 0; it < 4; it++) {
            int idx = tid + it * 256;
            int row = idx >> 3, ch = (idx & 7) * 4;
            int gr = m0 + row;
            int ok = (gr < M) ? 16 : 0;
            int grc = min(gr, M - 1);
            const float* src;
            if (RMA == 0) src = A + (size_t)grc * K + k0 + ch;
            else          src = arow<RMA>(A, grc) + k0 + ch;
            cp_async16(sA + (buf * A_TILE + row * ASTR + ch) * 4, src, ok);
        }
#pragma unroll
        for (int it = 0; it < 4; it++) {
            int idx = tid + it * 256;
            int row = idx >> 5, ch = (idx & 31) * 4;
            cp_async16(sB + (buf * B_TILE + row * BSTR + ch) * 4,
                       B + (size_t)(k0 + row) * N + n0 + ch, 16);
        }
        asm volatile("cp.async.commit_group;");
    };

    issue(0, 0);

    for (int t = 0; t < ntiles; t++) {
        int buf = t & 1;
        if (t + 1 < ntiles) {
            issue(t + 1, (t + 1) & 1);
            asm volatile("cp.async.wait_group 1;");
        } else {
            asm volatile("cp.async.wait_group 0;");
        }
        __syncthreads();

        const float* Bp = Bs + buf * B_TILE;
        uint32_t sAb = sA + buf * A_TILE * 4;
#pragma unroll
        for (int kk = 0; kk < 32; kk += 8) {
            uint32_t a[4][4];
#pragma unroll
            for (int i = 0; i < 4; i++) {
                asm volatile("ldmatrix.sync.aligned.m8n8.x4.shared.b16 {%0,%1,%2,%3}, [%4];"
                             : "=r"(a[i][0]), "=r"(a[i][1]), "=r"(a[i][2]), "=r"(a[i][3])
                             : "r"(sAb + aBase[i] + kk * 4));
            }
            uint32_t b[4][2];
#pragma unroll
            for (int j = 0; j < 4; j++) {
                b[j][0] = __float_as_uint(Bp[(kk + tig) * BSTR + bCol + j * 8]);
                b[j][1] = __float_as_uint(Bp[(kk + 4 + tig) * BSTR + bCol + j * 8]);
            }
#pragma unroll
            for (int i = 0; i < 4; i++)
#pragma unroll
                for (int j = 0; j < 4; j++) {
                    asm volatile(
                        "mma.sync.aligned.m16n8k8.row.col.f32.tf32.tf32.f32 "
                        "{%0,%1,%2,%3}, {%4,%5,%6,%7}, {%8,%9}, {%0,%1,%2,%3};"
                        : "+f"(c[i][j][0]), "+f"(c[i][j][1]),
                          "+f"(c[i][j][2]), "+f"(c[i][j][3])
                        : "r"(a[i][0]), "r"(a[i][1]), "r"(a[i][2]), "r"(a[i][3]),
                          "r"(b[j][0]), "r"(b[j][1]));
                }
        }
        __syncthreads();
    }

#pragma unroll
    for (int i = 0; i < 4; i++) {
        int r0 = m0 + wm * 64 + i * 16 + g;
#pragma unroll
        for (int j = 0; j < 4; j++) {
            int col = n0 + wn * 32 + j * 8 + 2 * tig;
#pragma unroll
            for (int half = 0; half < 2; half++) {
                int m = r0 + half * 8;
                if (m >= M) continue;
                float v0 = c[i][j][2 * half + 0];
                float v1 = c[i][j][2 * half + 1];
                if (EPI == 1) {
                    const float* Rrow = (RMR == 0) ? R + (size_t)m * N : arow<RMR>(R, m);
                    v0 += Rrow[col];
                    v1 += Rrow[col + 1];
                } else if (EPI == 2) {
                    v0 += bias[col];
                    v1 += bias[col + 1];
                    v0 = 0.5f * v0 * (1.f + erff(v0 * 0.70710678118654752f));
                    v1 = 0.5f * v1 * (1.f + erff(v1 * 0.70710678118654752f));
                } else if (EPI == 3) {
                    const float* Rrow = R + (size_t)m * N;
                    v0 += bias[col] + Rrow[col];
                    v1 += bias[col + 1] + Rrow[col + 1];
                }
                *(float2*)(C + (size_t)m * N + col) = make_float2(v0, v1);
            }
        }
    }
}

// ---------------- tensor-core attention pieces -------------------------------
#define KSTR 68    // QK B-loads: 32 distinct banks (4g+tig)
#define VSTR 72    // PV B-loads: 32 distinct banks (8tig+g)
#define PSTR 68
#define TKPAD 272
#define SMEM_AT ((TKPAD * KSTR + TKPAD * VSTR + 8 * 16 * PSTR) * 4)

__device__ __forceinline__ void mma8(float (&c)[4], const float (&a)[4],
                                     uint32_t b0, uint32_t b1) {
    asm volatile(
        "mma.sync.aligned.m16n8k8.row.col.f32.tf32.tf32.f32 "
        "{%0,%1,%2,%3}, {%4,%5,%6,%7}, {%8,%9}, {%0,%1,%2,%3};"
        : "+f"(c[0]), "+f"(c[1]), "+f"(c[2]), "+f"(c[3])
        : "r"(__float_as_uint(a[0])), "r"(__float_as_uint(a[1])),
          "r"(__float_as_uint(a[2])), "r"(__float_as_uint(a[3])),
          "r"(b0), "r"(b1));
}

template <int NTILE>
__device__ __forceinline__ void attn_kblock(
    const float* __restrict__ Ksb, const float* __restrict__ Vsb,
    float* __restrict__ Pw,
    const float (&qa)[8][4], float (&oc)[8][4],
    float& sum0, float& sum1,
    int g, int tig, int keybase, int klimit)
{
    float sc[NTILE][4];
#pragma unroll
    for (int nt = 0; nt < NTILE; nt++) {
        sc[nt][0] = sc[nt][1] = sc[nt][2] = sc[nt][3] = 0.f;
        const float* Kp = Ksb + (nt * 8 + g) * KSTR;
#pragma unroll
        for (int kk = 0; kk < 8; kk++) {
            uint32_t b0 = __float_as_uint(Kp[kk * 8 + tig]);
            uint32_t b1 = __float_as_uint(Kp[kk * 8 + tig + 4]);
            mma8(sc[nt], qa[kk], b0, b1);
        }
    }
#pragma unroll
    for (int nt = 0; nt < NTILE; nt++) {
        int key = keybase + nt * 8 + 2 * tig;
        float e0 = (key     < klimit) ? __expf(sc[nt][0]) : 0.f;
        float e1 = (key + 1 < klimit) ? __expf(sc[nt][1]) : 0.f;
        float e2 = (key     < klimit) ? __expf(sc[nt][2]) : 0.f;
        float e3 = (key + 1 < klimit) ? __expf(sc[nt][3]) : 0.f;
        sum0 += e0 + e1;
        sum1 += e2 + e3;
        *(float2*)(Pw + g * PSTR + nt * 8 + 2 * tig)       = make_float2(e0, e1);
        *(float2*)(Pw + (g + 8) * PSTR + nt * 8 + 2 * tig) = make_float2(e2, e3);
    }
    __syncwarp();
    float pa[NTILE][4];
#pragma unroll
    for (int kc = 0; kc < NTILE; kc++) {
        pa[kc][0] = Pw[g * PSTR + kc * 8 + tig];
        pa[kc][1] = Pw[(g + 8) * PSTR + kc * 8 + tig];
        pa[kc][2] = Pw[g * PSTR + kc * 8 + tig + 4];
        pa[kc][3] = Pw[(g + 8) * PSTR + kc * 8 + tig + 4];
    }
#pragma unroll
    for (int nt = 0; nt < 8; nt++) {
#pragma unroll
        for (int kc = 0; kc < NTILE; kc++) {
            const float* Vp = Vsb + (kc * 8 + tig) * VSTR + nt * 8 + g;
            uint32_t b0 = __float_as_uint(Vp[0]);
            uint32_t b1 = __float_as_uint(Vp[4 * VSTR]);
            mma8(oc[nt], pa[kc], b0, b1);
        }
    }
    __syncwarp();
}

// ---------------- temporal attention (mma) -----------------------------------
__global__ void __launch_bounds__(256) attn_t_mma() {
    extern __shared__ float sm[];
    float* Ks = sm;
    float* Vs = Ks + TKPAD * KSTR;
    float* Ps = Vs + TKPAD * VSTR;

    int b = blockIdx.x >> 3, h = blockIdx.x & 7;
    const float* base = g_QKV1 + (size_t)b * NT * 1536;

    for (int i = threadIdx.x; i < TKPAD * 16; i += 256) {
        int t = i >> 4, c4 = (i & 15) * 4;
        float4 kv = make_float4(0.f, 0.f, 0.f, 0.f);
        float4 vv = make_float4(0.f, 0.f, 0.f, 0.f);
        if (t < NT) {
            kv = *(const float4*)(base + (size_t)t * 1536 + 512 + h * 64 + c4);
            vv = *(const float4*)(base + (size_t)t * 1536 + 1024 + h * 64 + c4);
        }
        float* kd = Ks + t * KSTR + c4;
        kd[0] = kv.x; kd[1] = kv.y; kd[2] = kv.z; kd[3] = kv.w;
        float* vd = Vs + t * VSTR + c4;
        vd[0] = vv.x; vd[1] = vv.y; vd[2] = vv.z; vd[3] = vv.w;
    }
    __syncthreads();

    int lane = threadIdx.x & 31, warp = threadIdx.x >> 5;
    int g = lane >> 2, tig = lane & 3;
    float* Pw = Ps + warp * 16 * PSTR;

    for (int qt = warp; qt < 17; qt += 8) {
        int q0 = qt * 16;
        int r0 = min(q0 + g, NT - 1), r1 = min(q0 + g + 8, NT - 1);
        const float* Q0 = base + (size_t)r0 * 1536 + h * 64;
        const float* Q1 = base + (size_t)r1 * 1536 + h * 64;
        float qa[8][4];
#pragma unroll
        for (int kk = 0; kk < 8; kk++) {
            qa[kk][0] = Q0[kk * 8 + tig] * 0.125f;
            qa[kk][1] = Q1[kk * 8 + tig] * 0.125f;
            qa[kk][2] = Q0[kk * 8 + tig + 4] * 0.125f;
            qa[kk][3] = Q1[kk * 8 + tig + 4] * 0.125f;
        }
        float oc[8][4];
#pragma unroll
        for (int nt = 0; nt < 8; nt++)
            oc[nt][0] = oc[nt][1] = oc[nt][2] = oc[nt][3] = 0.f;
        float sum0 = 0.f, sum1 = 0.f;

#pragma unroll
        for (int kb = 0; kb < 4; kb++)
            attn_kblock<8>(Ks + kb * 64 * KSTR, Vs + kb * 64 * VSTR, Pw,
                           qa, oc, sum0, sum1, g, tig, kb * 64, NT);
        attn_kblock<2>(Ks + 256 * KSTR, Vs + 256 * VSTR, Pw,
                       qa, oc, sum0, sum1, g, tig, 256, NT);

        sum0 += __shfl_xor_sync(0xffffffffu, sum0, 1);
        sum0 += __shfl_xor_sync(0xffffffffu, sum0, 2);
        sum1 += __shfl_xor_sync(0xffffffffu, sum1, 1);
        sum1 += __shfl_xor_sync(0xffffffffu, sum1, 2);
        float inv0 = 1.f / sum0, inv1 = 1.f / sum1;

        int row0 = q0 + g, row1 = q0 + g + 8;
        if (row0 < NT) {
            float* op = g_O1 + ((size_t)b * NT + row0) * 512 + h * 64;
#pragma unroll
            for (int nt = 0; nt < 8; nt++)
                *(float2*)(op + nt * 8 + 2 * tig) =
                    make_float2(oc[nt][0] * inv0, oc[nt][1] * inv0);
        }
        if (row1 < NT) {
            float* op = g_O1 + ((size_t)b * NT + row1) * 512 + h * 64;
#pragma unroll
            for (int nt = 0; nt < 8; nt++)
                *(float2*)(op + nt * 8 + 2 * tig) =
                    make_float2(oc[nt][2] * inv1, oc[nt][3] * inv1);
        }
    }
}

// ---------------- fused spatial: E-projection (mma) + attention (mma) --------
#define ETSTR 76   // a-frag loads: 12g+tig -> 32 distinct banks
#define KVSTR 72   // b-frag loads: 8tig+g -> 32 distinct banks
#define SMEM_SF ((128 * ETSTR + 2 * 72 * KVSTR + KPROJ * KSTR + KPROJ * VSTR + 8 * 16 * PSTR) * 4)

__global__ void __launch_bounds__(256) attn_s_fused(const float* __restrict__ E) {
    extern __shared__ float sm[];
    float* ET   = sm;                        // [128][ETSTR]  E transposed, j-padded
    float* Ksrc = ET + 128 * ETSTR;          // [72][KVSTR]   raw K rows (j), padded
    float* Vsrc = Ksrc + 72 * KVSTR;         // [72][KVSTR]
    float* Ks   = Vsrc + 72 * KVSTR;         // [128][KSTR]   projected KE
    float* Vs   = Ks + KPROJ * KSTR;         // [128][VSTR]   projected VE
    float* Ps   = Vs + KPROJ * VSTR;

    int blk = blockIdx.x;           // fb*8 + h
    int fb = blk >> 3, h = blk & 7;
    const float* base = g_QKV2 + (size_t)fb * NS * 1536;

    // zero pads: ET cols j in [65,76), Ksrc/Vsrc rows 65..71
    for (int i = threadIdx.x; i < 128 * 11; i += 256) {
        int kk = i / 11, j = 65 + i % 11;
        ET[kk * ETSTR + j] = 0.f;
    }
    for (int i = threadIdx.x; i < 7 * KVSTR; i += 256) {
        Ksrc[65 * KVSTR + i] = 0.f;
        Vsrc[65 * KVSTR + i] = 0.f;
    }
    // load E transposed: ET[kk][j] = E[j][kk]
    for (int i = threadIdx.x; i < NS * 128; i += 256) {
        int j = i >> 7, kk = i & 127;
        ET[kk * ETSTR + j] = E[i];
    }
    // load raw K/V rows
    for (int i = threadIdx.x; i < NS * 16; i += 256) {
        int j = i >> 4, c4 = (i & 15) * 4;
        float4 kv = *(const float4*)(base + (size_t)j * 1536 + 512 + h * 64 + c4);
        float4 vv = *(const float4*)(base + (size_t)j * 1536 + 1024 + h * 64 + c4);
        float* kd = Ksrc + j * KVSTR + c4;
        kd[0] = kv.x; kd[1] = kv.y; kd[2] = kv.z; kd[3] = kv.w;
        float* vd = Vsrc + j * KVSTR + c4;
        vd[0] = vv.x; vd[1] = vv.y; vd[2] = vv.z; vd[3] = vv.w;
    }
    __syncthreads();

    int lane = threadIdx.x & 31, warp = threadIdx.x >> 5;
    int g = lane >> 2, tig = lane & 3;

    // phase 1: KE/VE = E^T (128x72) @ K/V (72x64) via mma, all 8 warps
    {
        int m0w = warp * 16;
        float ck[8][4], cv[8][4];
#pragma unroll
        for (int nf = 0; nf < 8; nf++) {
            ck[nf][0] = ck[nf][1] = ck[nf][2] = ck[nf][3] = 0.f;
            cv[nf][0] = cv[nf][1] = cv[nf][2] = cv[nf][3] = 0.f;
        }
#pragma unroll
        for (int ks = 0; ks < 9; ks++) {
            int j0 = ks * 8;
            float a[4];
            a[0] = ET[(m0w + g) * ETSTR + j0 + tig];
            a[1] = ET[(m0w + g + 8) * ETSTR + j0 + tig];
            a[2] = ET[(m0w + g) * ETSTR + j0 + tig + 4];
            a[3] = ET[(m0w + g + 8) * ETSTR + j0 + tig + 4];
#pragma unroll
            for (int nf = 0; nf < 8; nf++) {
                const float* Kp = Ksrc + (j0 + tig) * KVSTR + nf * 8 + g;
                mma8(ck[nf], a, __float_as_uint(Kp[0]), __float_as_uint(Kp[4 * KVSTR]));
                const float* Vp = Vsrc + (j0 + tig) * KVSTR + nf * 8 + g;
                mma8(cv[nf], a, __float_as_uint(Vp[0]), __float_as_uint(Vp[4 * KVSTR]));
            }
        }
#pragma unroll
        for (int nf = 0; nf < 8; nf++) {
            int col = nf * 8 + 2 * tig;
            *(float2*)(Ks + (m0w + g) * KSTR + col)     = make_float2(ck[nf][0], ck[nf][1]);
            *(float2*)(Ks + (m0w + g + 8) * KSTR + col) = make_float2(ck[nf][2], ck[nf][3]);
            *(float2*)(Vs + (m0w + g) * VSTR + col)     = make_float2(cv[nf][0], cv[nf][1]);
            *(float2*)(Vs + (m0w + g + 8) * VSTR + col) = make_float2(cv[nf][2], cv[nf][3]);
        }
    }
    __syncthreads();

    // phase 2: attention over 128 projected keys
    float* Pw = Ps + warp * 16 * PSTR;
    for (int qt = warp; qt < 5; qt += 8) {
        int q0 = qt * 16;
        int r0 = min(q0 + g, NS - 1), r1 = min(q0 + g + 8, NS - 1);
        const float* Q0 = base + (size_t)r0 * 1536 + h * 64;
        const float* Q1 = base + (size_t)r1 * 1536 + h * 64;
        float qa[8][4];
#pragma unroll
        for (int kk = 0; kk < 8; kk++) {
            qa[kk][0] = Q0[kk * 8 + tig] * 0.125f;
            qa[kk][1] = Q1[kk * 8 + tig] * 0.125f;
            qa[kk][2] = Q0[kk * 8 + tig + 4] * 0.125f;
            qa[kk][3] = Q1[kk * 8 + tig + 4] * 0.125f;
        }
        float oc[8][4];
#pragma unroll
        for (int nt = 0; nt < 8; nt++)
            oc[nt][0] = oc[nt][1] = oc[nt][2] = oc[nt][3] = 0.f;
        float sum0 = 0.f, sum1 = 0.f;

        attn_kblock<8>(Ks, Vs, Pw, qa, oc, sum0, sum1, g, tig, 0, KPROJ);
        attn_kblock<8>(Ks + 64 * KSTR, Vs + 64 * VSTR, Pw,
                       qa, oc, sum0, sum1, g, tig, 64, KPROJ);

        sum0 += __shfl_xor_sync(0xffffffffu, sum0, 1);
        sum0 += __shfl_xor_sync(0xffffffffu, sum0, 2);
        sum1 += __shfl_xor_sync(0xffffffffu, sum1, 1);
        sum1 += __shfl_xor_sync(0xffffffffu, sum1, 2);
        float inv0 = 1.f / sum0, inv1 = 1.f / sum1;

        int row0 = q0 + g, row1 = q0 + g + 8;
        if (row0 < NS) {
            float* op = g_O2 + ((size_t)fb * NS + row0) * 512 + h * 64;
#pragma unroll
            for (int nt = 0; nt < 8; nt++)
                *(float2*)(op + nt * 8 + 2 * tig) =
                    make_float2(oc[nt][0] * inv0, oc[nt][1] * inv0);
        }
        if (row1 < NS) {
            float* op = g_O2 + ((size_t)fb * NS + row1) * 512 + h * 64;
#pragma unroll
            for (int nt = 0; nt < 8; nt++)
                *(float2*)(op + nt * 8 + 2 * tig) =
                    make_float2(oc[nt][2] * inv1, oc[nt][3] * inv1);
        }
    }
}

// ---------------- launch -----------------------------------------------------
extern "C" void kernel_launch(void* const* d_in, const int* in_sizes, int n_in,
                              void* d_out, int out_size) {
    const float* x      = (const float*)d_in[0];
    const float* Wqkv_t = (const float*)d_in[1];
    const float* Wo_t   = (const float*)d_in[2];
    const float* Wqkv_s = (const float*)d_in[3];
    const float* Wo_s   = (const float*)d_in[4];
    const float* E      = (const float*)d_in[5];
    const float* W1     = (const float*)d_in[6];
    const float* b1     = (const float*)d_in[7];
    const float* W2     = (const float*)d_in[8];
    const float* b2     = (const float*)d_in[9];
    float* out = (float*)d_out;
    (void)in_sizes; (void)n_in; (void)out_size;

    float *QKV1, *O1, *Y1, *QKV2, *O2, *Y2, *H;
    cudaGetSymbolAddress((void**)&QKV1, g_QKV1);
    cudaGetSymbolAddress((void**)&O1, g_O1);
    cudaGetSymbolAddress((void**)&Y1, g_Y1);
    cudaGetSymbolAddress((void**)&QKV2, g_QKV2);
    cudaGetSymbolAddress((void**)&O2, g_O2);
    cudaGetSymbolAddress((void**)&Y2, g_Y2);
    cudaGetSymbolAddress((void**)&H, g_H);

    cudaFuncSetAttribute(attn_t_mma, cudaFuncAttributeMaxDynamicSharedMemorySize, SMEM_AT);
    cudaFuncSetAttribute(attn_s_fused, cudaFuncAttributeMaxDynamicSharedMemorySize, SMEM_SF);
    cudaFuncSetAttribute((tf32_gemm<0,1,0>), cudaFuncAttributeMaxDynamicSharedMemorySize, GEMM_SMEM);
    cudaFuncSetAttribute((tf32_gemm<1,0,1>), cudaFuncAttributeMaxDynamicSharedMemorySize, GEMM_SMEM);
    cudaFuncSetAttribute((tf32_gemm<0,2,0>), cudaFuncAttributeMaxDynamicSharedMemorySize, GEMM_SMEM);
    cudaFuncSetAttribute((tf32_gemm<1,0,2>), cudaFuncAttributeMaxDynamicSharedMemorySize, GEMM_SMEM);
    cudaFuncSetAttribute((tf32_gemm<2,0,0>), cudaFuncAttributeMaxDynamicSharedMemorySize, GEMM_SMEM);
    cudaFuncSetAttribute((tf32_gemm<3,0,0>), cudaFuncAttributeMaxDynamicSharedMemorySize, GEMM_SMEM);

    // ---- temporal stage (gather folded into A/R remaps) ----
    tf32_gemm<0,1,0><<<dim3(3 * DIMX / 128, (MT + 127) / 128), 256, GEMM_SMEM>>>(
        x, Wqkv_t, QKV1, nullptr, nullptr, MT, 3 * DIMX, DIMX);
    attn_t_mma<<<PATCHES * HEADS, 256, SMEM_AT>>>();
    tf32_gemm<1,0,1><<<dim3(DIMX / 128, (MT + 127) / 128), 256, GEMM_SMEM>>>(
        O1, Wo_t, Y1, nullptr, x, MT, DIMX, DIMX);

    // ---- spatial stage ----
    tf32_gemm<0,2,0><<<dim3(3 * DIMX / 128, MS / 128), 256, GEMM_SMEM>>>(
        Y1, Wqkv_s, QKV2, nullptr, nullptr, MS, 3 * DIMX, DIMX);
    attn_s_fused<<<FRAMES * HEADS, 256, SMEM_SF>>>(E);
    tf32_gemm<1,0,2><<<dim3(DIMX / 128, MS / 128), 256, GEMM_SMEM>>>(
        O2, Wo_s, Y2, nullptr, Y1, MS, DIMX, DIMX);

    // ---- FFN ----
    tf32_gemm<2,0,0><<<dim3(DFF / 128, MS / 128), 256, GEMM_SMEM>>>(
        Y2, W1, H, b1, nullptr, MS, DFF, DIMX);
    tf32_gemm<3,0,0><<<dim3(DIMX / 128, MS / 128), 256, GEMM_SMEM>>>(
        H, W2, out, b2, Y2, MS, DIMX, DFF);
}